// round 14
// baseline (speedup 1.0000x reference)
#include <cuda_runtime.h>
#include <cuda_bf16.h>
#include <cstdint>

// Shapes (fixed by problem)
#define Bq   4
#define Lq   2048
#define Dq   768
#define DIq  1536
#define DSq  16
#define DRq  48
#define BLq  8192          // B*L
#define TWOD 1536          // 2*D
#define THREED 2304        // 3*D

// ---------------- scratch (static device memory; no allocation) ----------------
__device__ float g_ada[Bq * THREED];                 // [b][3D]  shift|scale|gate
__device__ float g_xm [BLq * Dq];                    // [bl][D]   modulated LN output
__device__ float g_xi [Bq * DIq * Lq];               // [b][d][l]
__device__ float g_z  [Bq * DIq * Lq];               // [b][d][l]
__device__ float g_u  [Bq * DIq * Lq];               // [b][d][l]  silu(conv)
__device__ float g_dt [BLq * DRq];                   // [bl][48]
__device__ float g_Bm [BLq * DSq];                   // [bl][16]
__device__ float g_Cm [BLq * DSq];                   // [bl][16]
__device__ float g_delta[Bq * DIq * Lq];             // [b][d][l]
__device__ float g_y  [Bq * DIq * Lq];               // [b][d][l]  gated scan output

__device__ __forceinline__ float silu_f(float x) {
    return x / (1.0f + __expf(-x));
}
__device__ __forceinline__ float softplus_f(float x) {
    return (x > 20.0f) ? x : log1pf(__expf(x));
}
__device__ __forceinline__ uint32_t f2tf32(float x) {
    uint32_t r;
    asm("cvt.rna.tf32.f32 %0, %1;" : "=r"(r) : "f"(x));
    return r;
}
__device__ __forceinline__ uint32_t f2bf2(float lo, float hi) {
    __nv_bfloat162 v = __floats2bfloat162_rn(lo, hi);
    return *(uint32_t*)&v;
}
__device__ __forceinline__ void mma_tf32(float (&d)[4], const uint32_t* a, const uint32_t* b) {
    asm volatile("mma.sync.aligned.m16n8k8.row.col.f32.tf32.tf32.f32 "
        "{%0,%1,%2,%3},{%4,%5,%6,%7},{%8,%9},{%0,%1,%2,%3};"
        : "+f"(d[0]), "+f"(d[1]), "+f"(d[2]), "+f"(d[3])
        : "r"(a[0]), "r"(a[1]), "r"(a[2]), "r"(a[3]), "r"(b[0]), "r"(b[1]));
}
__device__ __forceinline__ void mma_bf16(float (&d)[4], const uint32_t* a, const uint32_t* b) {
    asm volatile("mma.sync.aligned.m16n8k16.row.col.f32.bf16.bf16.f32 "
        "{%0,%1,%2,%3},{%4,%5,%6,%7},{%8,%9},{%0,%1,%2,%3};"
        : "+f"(d[0]), "+f"(d[1]), "+f"(d[2]), "+f"(d[3])
        : "r"(a[0]), "r"(a[1]), "r"(a[2]), "r"(a[3]), "r"(b[0]), "r"(b[1]));
}

// ---------------- instrumentation nop (shifts gemm_xz_bf into profiled slot #4)
__global__ void k_nop() {}

// ---------------- ada = silu(c) @ ada_w.T + ada_b ----------------
__global__ void k_ada(const float* __restrict__ c,
                      const float* __restrict__ ada_w,
                      const float* __restrict__ ada_b) {
    __shared__ float sc[Bq * TWOD];
    int tid = threadIdx.x;
    for (int i = tid; i < Bq * TWOD; i += blockDim.x) {
        float v = c[i];
        sc[i] = silu_f(v);
    }
    __syncthreads();
    int j = blockIdx.x * blockDim.x + tid;
    if (j >= THREED) return;
    float a0 = 0.f, a1 = 0.f, a2 = 0.f, a3 = 0.f;
    const float* w = ada_w + (size_t)j * TWOD;
    #pragma unroll 4
    for (int k = 0; k < TWOD; k += 4) {
        float4 wv = *(const float4*)(w + k);
        a0 += wv.x*sc[0*TWOD+k] + wv.y*sc[0*TWOD+k+1] + wv.z*sc[0*TWOD+k+2] + wv.w*sc[0*TWOD+k+3];
        a1 += wv.x*sc[1*TWOD+k] + wv.y*sc[1*TWOD+k+1] + wv.z*sc[1*TWOD+k+2] + wv.w*sc[1*TWOD+k+3];
        a2 += wv.x*sc[2*TWOD+k] + wv.y*sc[2*TWOD+k+1] + wv.z*sc[2*TWOD+k+2] + wv.w*sc[2*TWOD+k+3];
        a3 += wv.x*sc[3*TWOD+k] + wv.y*sc[3*TWOD+k+1] + wv.z*sc[3*TWOD+k+2] + wv.w*sc[3*TWOD+k+3];
    }
    float bb = ada_b[j];
    g_ada[0*THREED + j] = a0 + bb;
    g_ada[1*THREED + j] = a1 + bb;
    g_ada[2*THREED + j] = a2 + bb;
    g_ada[3*THREED + j] = a3 + bb;
}

// ---------------- LayerNorm + modulation ----------------
__global__ void k_ln(const float* __restrict__ x,
                     const float* __restrict__ ln_w,
                     const float* __restrict__ ln_b) {
    int row = blockIdx.x;            // bl
    int b = row >> 11;
    const float* xr = x + (size_t)row * Dq;
    int tid = threadIdx.x;
    float v0 = xr[tid], v1 = xr[tid + 256], v2 = xr[tid + 512];
    float s = v0 + v1 + v2;
    float sq = v0*v0 + v1*v1 + v2*v2;
    #pragma unroll
    for (int o = 16; o; o >>= 1) {
        s  += __shfl_xor_sync(0xffffffffu, s, o);
        sq += __shfl_xor_sync(0xffffffffu, sq, o);
    }
    __shared__ float ss[8], sqq[8];
    int lane = tid & 31, wid = tid >> 5;
    if (lane == 0) { ss[wid] = s; sqq[wid] = sq; }
    __syncthreads();
    float ts = 0.f, tq = 0.f;
    #pragma unroll
    for (int w = 0; w < 8; ++w) { ts += ss[w]; tq += sqq[w]; }
    float mu = ts * (1.0f / Dq);
    float var = tq * (1.0f / Dq) - mu * mu;
    float rs = rsqrtf(var + 1e-5f);
    float* dst = g_xm + (size_t)row * Dq;
    const float* sh = g_ada + b * THREED;        // shift
    const float* sc = g_ada + b * THREED + Dq;   // scale
    #pragma unroll
    for (int p = 0; p < 3; ++p) {
        int i = tid + p * 256;
        float v = (p == 0) ? v0 : (p == 1) ? v1 : v2;
        float xn = (v - mu) * rs * ln_w[i] + ln_b[i];
        dst[i] = xn * (1.0f + sc[i]) + sh[i];
    }
}

// ======================= bf16 m16n8k16 tensor-core GEMMs =======================
// Block tile 128x128, BK=16 (8 k-pair rows), 8 warps (2x4), warp 64x32.
#define SST 136   // smem row stride in words (8-bank rotation per kpair row)

// xz = xm @ in_proj_w.T. A=in_proj_w (3072x768) k-fastest, B=g_xm (8192x768) k-fastest.
__global__ void __launch_bounds__(256)
gemm_xz_bf(const float* __restrict__ W) {
    __shared__ uint32_t As[8][SST];
    __shared__ uint32_t Bs[8][SST];
    const int K = Dq;
    int tid = threadIdx.x;
    int warp = tid >> 5, lane = tid & 31;
    int g = lane >> 2, t = lane & 3;
    int wm = (warp >> 2) * 64;
    int wn = (warp & 3) * 32;
    int nBase = blockIdx.y * 128;   // over 3072 (W rows)
    int mBase = blockIdx.x * 128;   // over 8192 (bl)
    float acc[4][4][4];
    #pragma unroll
    for (int i = 0; i < 4; ++i)
        #pragma unroll
        for (int j = 0; j < 4; ++j)
            #pragma unroll
            for (int r = 0; r < 4; ++r) acc[i][j][r] = 0.f;

    int lrow = tid >> 2;          // 0..63
    int lk   = (tid & 3) * 4;     // k offset within 16
    int kp   = lk >> 1;           // kpair row: 0,2,4,6
    float4 pa[2], pb[2];
    #pragma unroll
    for (int h = 0; h < 2; ++h) {
        pa[h] = *(const float4*)&W   [(size_t)(nBase + lrow + h*64) * K + lk];
        pb[h] = *(const float4*)&g_xm[(size_t)(mBase + lrow + h*64) * K + lk];
    }
    for (int k0 = 0; k0 < K; k0 += 16) {
        #pragma unroll
        for (int h = 0; h < 2; ++h) {
            int r = lrow + h * 64;
            As[kp+0][r] = f2bf2(pa[h].x, pa[h].y);
            As[kp+1][r] = f2bf2(pa[h].z, pa[h].w);
            Bs[kp+0][r] = f2bf2(pb[h].x, pb[h].y);
            Bs[kp+1][r] = f2bf2(pb[h].z, pb[h].w);
        }
        __syncthreads();
        if (k0 + 16 < K) {
            #pragma unroll
            for (int h = 0; h < 2; ++h) {
                pa[h] = *(const float4*)&W   [(size_t)(nBase + lrow + h*64) * K + k0 + 16 + lk];
                pb[h] = *(const float4*)&g_xm[(size_t)(mBase + lrow + h*64) * K + k0 + 16 + lk];
            }
        }
        {
            uint32_t af[4][4], bf[4][2];
            #pragma unroll
            for (int mi = 0; mi < 4; ++mi) {
                int mr = wm + mi * 16 + g;
                af[mi][0] = As[t][mr];     af[mi][1] = As[t][mr+8];
                af[mi][2] = As[t+4][mr];   af[mi][3] = As[t+4][mr+8];
            }
            #pragma unroll
            for (int ni = 0; ni < 4; ++ni) {
                int nc = wn + ni * 8 + g;
                bf[ni][0] = Bs[t][nc];
                bf[ni][1] = Bs[t+4][nc];
            }
            #pragma unroll
            for (int mi = 0; mi < 4; ++mi)
                #pragma unroll
                for (int ni = 0; ni < 4; ++ni)
                    mma_bf16(acc[mi][ni], af[mi], bf[ni]);
        }
        __syncthreads();
    }
    int b = mBase >> 11;
    int l0 = (mBase & 2047) + wn;
    #pragma unroll
    for (int mi = 0; mi < 4; ++mi) {
        int n = nBase + wm + mi * 16 + g;
        #pragma unroll
        for (int ni = 0; ni < 4; ++ni) {
            int l = l0 + ni * 8 + 2 * t;
            float* d0 = (n < DIq) ? &g_xi[((size_t)b*DIq + n)*Lq]
                                  : &g_z [((size_t)b*DIq + (n - DIq))*Lq];
            int n2 = n + 8;
            float* d1 = (n2 < DIq) ? &g_xi[((size_t)b*DIq + n2)*Lq]
                                   : &g_z [((size_t)b*DIq + (n2 - DIq))*Lq];
            *(float2*)&d0[l] = make_float2(acc[mi][ni][0], acc[mi][ni][1]);
            *(float2*)&d1[l] = make_float2(acc[mi][ni][2], acc[mi][ni][3]);
        }
    }
}

// out = g @ out_proj_w.T (+x +gate*...). A=out_proj_w (768x1536) k-fastest,
// B = g_y[b][d][l] (k = d rows, cols = l; k-pairs pack two adjacent d rows).
__global__ void __launch_bounds__(256)
gemm_out_bf(const float* __restrict__ Wo, const float* __restrict__ x,
            float* __restrict__ out) {
    __shared__ uint32_t As[8][SST];
    __shared__ uint32_t Bs[8][SST];
    const int K = DIq;
    int tid = threadIdx.x;
    int warp = tid >> 5, lane = tid & 31;
    int g = lane >> 2, t = lane & 3;
    int wm = (warp >> 2) * 64;
    int wn = (warp & 3) * 32;
    int nBase = blockIdx.y * 128;   // over 768 (channels)
    int mBase = blockIdx.x * 128;   // over 8192 (bl)
    int b = mBase >> 11;
    int l0b = mBase & 2047;
    float acc[4][4][4];
    #pragma unroll
    for (int i = 0; i < 4; ++i)
        #pragma unroll
        for (int j = 0; j < 4; ++j)
            #pragma unroll
            for (int r = 0; r < 4; ++r) acc[i][j][r] = 0.f;

    int lrow = tid >> 2;            // A loader
    int lk   = (tid & 3) * 4;
    int kp   = lk >> 1;
    int kp8  = tid >> 5;            // B loader: kpair row 0..7 (one per warp)
    int c4   = (tid & 31) * 4;      // B loader: col 0..124
    float4 pa[2], pbe, pbo;
    #pragma unroll
    for (int h = 0; h < 2; ++h)
        pa[h] = *(const float4*)&Wo[(size_t)(nBase + lrow + h*64) * K + lk];
    pbe = *(const float4*)&g_y[((size_t)b*DIq + 2*kp8    )*Lq + l0b + c4];
    pbo = *(const float4*)&g_y[((size_t)b*DIq + 2*kp8 + 1)*Lq + l0b + c4];
    for (int k0 = 0; k0 < K; k0 += 16) {
        #pragma unroll
        for (int h = 0; h < 2; ++h) {
            int r = lrow + h * 64;
            As[kp+0][r] = f2bf2(pa[h].x, pa[h].y);
            As[kp+1][r] = f2bf2(pa[h].z, pa[h].w);
        }
        {
            uint4 wv;
            wv.x = f2bf2(pbe.x, pbo.x);
            wv.y = f2bf2(pbe.y, pbo.y);
            wv.z = f2bf2(pbe.z, pbo.z);
            wv.w = f2bf2(pbe.w, pbo.w);
            *(uint4*)&Bs[kp8][c4] = wv;
        }
        __syncthreads();
        if (k0 + 16 < K) {
            #pragma unroll
            for (int h = 0; h < 2; ++h)
                pa[h] = *(const float4*)&Wo[(size_t)(nBase + lrow + h*64) * K + k0 + 16 + lk];
            pbe = *(const float4*)&g_y[((size_t)b*DIq + k0 + 16 + 2*kp8    )*Lq + l0b + c4];
            pbo = *(const float4*)&g_y[((size_t)b*DIq + k0 + 16 + 2*kp8 + 1)*Lq + l0b + c4];
        }
        {
            uint32_t af[4][4], bf[4][2];
            #pragma unroll
            for (int mi = 0; mi < 4; ++mi) {
                int mr = wm + mi * 16 + g;
                af[mi][0] = As[t][mr];     af[mi][1] = As[t][mr+8];
                af[mi][2] = As[t+4][mr];   af[mi][3] = As[t+4][mr+8];
            }
            #pragma unroll
            for (int ni = 0; ni < 4; ++ni) {
                int nc = wn + ni * 8 + g;
                bf[ni][0] = Bs[t][nc];
                bf[ni][1] = Bs[t+4][nc];
            }
            #pragma unroll
            for (int mi = 0; mi < 4; ++mi)
                #pragma unroll
                for (int ni = 0; ni < 4; ++ni)
                    mma_bf16(acc[mi][ni], af[mi], bf[ni]);
        }
        __syncthreads();
    }
    const float* gate = g_ada + b * THREED + 2 * Dq;
    #pragma unroll
    for (int mi = 0; mi < 4; ++mi) {
        int n = nBase + wm + mi * 16 + g;
        float g0 = gate[n], g1 = gate[n + 8];
        #pragma unroll
        for (int ni = 0; ni < 4; ++ni) {
            int m = mBase + wn + ni * 8 + 2 * t;
            out[(size_t)m*Dq + n]       = x[(size_t)m*Dq + n]       + g0 * acc[mi][ni][0];
            out[(size_t)(m+1)*Dq + n]   = x[(size_t)(m+1)*Dq + n]   + g0 * acc[mi][ni][1];
            out[(size_t)m*Dq + n+8]     = x[(size_t)m*Dq + n+8]     + g1 * acc[mi][ni][2];
            out[(size_t)(m+1)*Dq + n+8] = x[(size_t)(m+1)*Dq + n+8] + g1 * acc[mi][ni][3];
        }
    }
}

// dbl = u @ x_proj_w.T scattered into g_dt/g_Bm/g_Cm.
__device__ __forceinline__ void store_dbl(int n, int m, float v) {
    if (n < DRq)             g_dt[(size_t)m * DRq + n] = v;
    else if (n < DRq + DSq)  g_Bm[(size_t)m * DSq + (n - DRq)] = v;
    else if (n < 80)         g_Cm[(size_t)m * DSq + (n - DRq - DSq)] = v;
}
__global__ void __launch_bounds__(256)
gemm_dbl_bf(const float* __restrict__ Wx) {
    __shared__ uint32_t As[8][SST];
    __shared__ uint32_t Bs[8][SST];
    const int K = DIq;
    int tid = threadIdx.x;
    int warp = tid >> 5, lane = tid & 31;
    int g = lane >> 2, t = lane & 3;
    int wm = (warp >> 2) * 64;
    int wn = (warp & 3) * 32;
    int mBase = blockIdx.x * 128;   // over 8192 (bl)
    int b = mBase >> 11;
    int l0b = mBase & 2047;
    float acc[4][4][4];
    #pragma unroll
    for (int i = 0; i < 4; ++i)
        #pragma unroll
        for (int j = 0; j < 4; ++j)
            #pragma unroll
            for (int r = 0; r < 4; ++r) acc[i][j][r] = 0.f;

    int lrow = tid >> 2;
    int lk   = (tid & 3) * 4;
    int kp   = lk >> 1;
    int kp8  = tid >> 5;
    int c4   = (tid & 31) * 4;
    int ar0 = min(lrow, 79);        // clamp padded weight rows
    int ar1 = min(lrow + 64, 79);
    float4 pa[2], pbe, pbo;
    pa[0] = *(const float4*)&Wx[(size_t)ar0 * K + lk];
    pa[1] = *(const float4*)&Wx[(size_t)ar1 * K + lk];
    pbe = *(const float4*)&g_u[((size_t)b*DIq + 2*kp8    )*Lq + l0b + c4];
    pbo = *(const float4*)&g_u[((size_t)b*DIq + 2*kp8 + 1)*Lq + l0b + c4];
    for (int k0 = 0; k0 < K; k0 += 16) {
        #pragma unroll
        for (int h = 0; h < 2; ++h) {
            int r = lrow + h * 64;
            const float4& v = pa[h];
            As[kp+0][r] = f2bf2(v.x, v.y);
            As[kp+1][r] = f2bf2(v.z, v.w);
        }
        {
            uint4 wv;
            wv.x = f2bf2(pbe.x, pbo.x);
            wv.y = f2bf2(pbe.y, pbo.y);
            wv.z = f2bf2(pbe.z, pbo.z);
            wv.w = f2bf2(pbe.w, pbo.w);
            *(uint4*)&Bs[kp8][c4] = wv;
        }
        __syncthreads();
        if (k0 + 16 < K) {
            pa[0] = *(const float4*)&Wx[(size_t)ar0 * K + k0 + 16 + lk];
            pa[1] = *(const float4*)&Wx[(size_t)ar1 * K + k0 + 16 + lk];
            pbe = *(const float4*)&g_u[((size_t)b*DIq + k0 + 16 + 2*kp8    )*Lq + l0b + c4];
            pbo = *(const float4*)&g_u[((size_t)b*DIq + k0 + 16 + 2*kp8 + 1)*Lq + l0b + c4];
        }
        {
            uint32_t af[4][4], bf[4][2];
            #pragma unroll
            for (int mi = 0; mi < 4; ++mi) {
                int mr = wm + mi * 16 + g;
                af[mi][0] = As[t][mr];     af[mi][1] = As[t][mr+8];
                af[mi][2] = As[t+4][mr];   af[mi][3] = As[t+4][mr+8];
            }
            #pragma unroll
            for (int ni = 0; ni < 4; ++ni) {
                int nc = wn + ni * 8 + g;
                bf[ni][0] = Bs[t][nc];
                bf[ni][1] = Bs[t+4][nc];
            }
            #pragma unroll
            for (int mi = 0; mi < 4; ++mi)
                #pragma unroll
                for (int ni = 0; ni < 4; ++ni)
                    mma_bf16(acc[mi][ni], af[mi], bf[ni]);
        }
        __syncthreads();
    }
    #pragma unroll
    for (int mi = 0; mi < 4; ++mi) {
        int n = wm + mi * 16 + g;
        if (n >= 80 && n + 8 >= 80) continue;
        #pragma unroll
        for (int ni = 0; ni < 4; ++ni) {
            int m = mBase + wn + ni * 8 + 2 * t;
            store_dbl(n,     m,     acc[mi][ni][0]);
            store_dbl(n,     m + 1, acc[mi][ni][1]);
            store_dbl(n + 8, m,     acc[mi][ni][2]);
            store_dbl(n + 8, m + 1, acc[mi][ni][3]);
        }
    }
}

// ======================= TF32 delta GEMM (unchanged, passing) ===================
#define SSTD 136
__global__ void __launch_bounds__(256)
gemm_delta_tc(const float* __restrict__ Wd, const float* __restrict__ dt_b) {
    __shared__ uint32_t As[16][SSTD];
    __shared__ uint32_t Bs[16][SSTD];
    const int K = DRq;              // 48
    int tid = threadIdx.x;
    int warp = tid >> 5, lane = tid & 31;
    int g = lane >> 2, t = lane & 3;
    int wm = (warp >> 2) * 64;
    int wn = (warp & 3) * 32;
    int nBase = blockIdx.y * 128;
    int mBase = blockIdx.x * 128;
    float acc[4][4][4];
    #pragma unroll
    for (int i = 0; i < 4; ++i)
        #pragma unroll
        for (int j = 0; j < 4; ++j)
            #pragma unroll
            for (int r = 0; r < 4; ++r) acc[i][j][r] = 0.f;

    int lrow = tid >> 2;
    int lk   = (tid & 3) * 4;
    float4 pa[2], pb[2];
    #pragma unroll
    for (int h = 0; h < 2; ++h) {
        pa[h] = *(const float4*)&Wd  [(size_t)(nBase + lrow + h*64) * K + lk];
        pb[h] = *(const float4*)&g_dt[(size_t)(mBase + lrow + h*64) * K + lk];
    }
    for (int k0 = 0; k0 < K; k0 += 16) {
        #pragma unroll
        for (int h = 0; h < 2; ++h) {
            int r = lrow + h * 64;
            As[lk+0][r] = f2tf32(pa[h].x); As[lk+1][r] = f2tf32(pa[h].y);
            As[lk+2][r] = f2tf32(pa[h].z); As[lk+3][r] = f2tf32(pa[h].w);
            Bs[lk+0][r] = f2tf32(pb[h].x); Bs[lk+1][r] = f2tf32(pb[h].y);
            Bs[lk+2][r] = f2tf32(pb[h].z); Bs[lk+3][r] = f2tf32(pb[h].w);
        }
        __syncthreads();
        if (k0 + 16 < K) {
            #pragma unroll
            for (int h = 0; h < 2; ++h) {
                pa[h] = *(const float4*)&Wd  [(size_t)(nBase + lrow + h*64) * K + k0 + 16 + lk];
                pb[h] = *(const float4*)&g_dt[(size_t)(mBase + lrow + h*64) * K + k0 + 16 + lk];
            }
        }
        #pragma unroll
        for (int kk = 0; kk < 16; kk += 8) {
            uint32_t af[4][4], bf[4][2];
            #pragma unroll
            for (int mi = 0; mi < 4; ++mi) {
                int mr = wm + mi * 16 + g;
                af[mi][0] = As[kk+t][mr];     af[mi][1] = As[kk+t][mr+8];
                af[mi][2] = As[kk+t+4][mr];   af[mi][3] = As[kk+t+4][mr+8];
            }
            #pragma unroll
            for (int ni = 0; ni < 4; ++ni) {
                int nc = wn + ni * 8 + g;
                bf[ni][0] = Bs[kk+t][nc];
                bf[ni][1] = Bs[kk+t+4][nc];
            }
            #pragma unroll
            for (int mi = 0; mi < 4; ++mi)
                #pragma unroll
                for (int ni = 0; ni < 4; ++ni)
                    mma_tf32(acc[mi][ni], af[mi], bf[ni]);
        }
        __syncthreads();
    }
    int b = mBase >> 11;
    int l0 = (mBase & 2047) + wn;
    #pragma unroll
    for (int mi = 0; mi < 4; ++mi) {
        int n = nBase + wm + mi * 16 + g;
        float b0 = dt_b[n], b1 = dt_b[n + 8];
        float* d0 = &g_delta[((size_t)b*DIq + n)*Lq];
        float* d1 = &g_delta[((size_t)b*DIq + n + 8)*Lq];
        #pragma unroll
        for (int ni = 0; ni < 4; ++ni) {
            int l = l0 + ni * 8 + 2 * t;
            *(float2*)&d0[l] = make_float2(softplus_f(acc[mi][ni][0] + b0),
                                           softplus_f(acc[mi][ni][1] + b0));
            *(float2*)&d1[l] = make_float2(softplus_f(acc[mi][ni][2] + b1),
                                           softplus_f(acc[mi][ni][3] + b1));
        }
    }
}

// ---------------- depthwise causal conv(K=4) + SiLU -> u ----------------
__global__ void k_conv(const float* __restrict__ conv_w,
                       const float* __restrict__ conv_b) {
    int d = blockIdx.x, b = blockIdx.y;
    __shared__ float s[Lq + 4];
    const float* src = &g_xi[((size_t)b*DIq + d)*Lq];
    int tid = threadIdx.x;
    if (tid < 3) s[tid + 1] = 0.f;
    *(float4*)&s[4 + tid*8]     = *(const float4*)&src[tid*8];
    *(float4*)&s[4 + tid*8 + 4] = *(const float4*)&src[tid*8 + 4];
    __syncthreads();
    float w0 = conv_w[d*4+0], w1 = conv_w[d*4+1], w2 = conv_w[d*4+2], w3 = conv_w[d*4+3];
    float cb = conv_b[d];
    float out[8];
    int base = tid * 8;
    #pragma unroll
    for (int i = 0; i < 8; ++i) {
        int l = base + i;
        float acc = w0*s[l+1] + w1*s[l+2] + w2*s[l+3] + w3*s[l+4] + cb;
        out[i] = silu_f(acc);
    }
    float* dst = &g_u[((size_t)b*DIq + d)*Lq + base];
    *(float4*)&dst[0] = make_float4(out[0], out[1], out[2], out[3]);
    *(float4*)&dst[4] = make_float4(out[4], out[5], out[6], out[7]);
}

// ---------------- selective scan + fused gate ----------------
__global__ void k_scan(const float* __restrict__ A_log,
                       const float* __restrict__ D_param) {
    int b = blockIdx.y;
    int d0 = blockIdx.x * 16;
    int tid = threadIdx.x;
    int ld = tid >> 4, s = tid & 15;
    int d = d0 + ld;
    float A = -__expf(A_log[d * DSq + s]);
    const float* dptr = &g_delta[((size_t)b*DIq + d)*Lq];
    const float* uptr = &g_u   [((size_t)b*DIq + d)*Lq];
    const float* Bptr = &g_Bm[(size_t)b*Lq*DSq + s];
    const float* Cptr = &g_Cm[(size_t)b*Lq*DSq + s];
    __shared__ float ybuf[16][64];
    float h = 0.f;
    for (int t0 = 0; t0 < Lq; t0 += 64) {
        #pragma unroll 4
        for (int tc = 0; tc < 64; ++tc) {
            int t = t0 + tc;
            float dt = __ldg(dptr + t);
            float ut = __ldg(uptr + t);
            float Bt = __ldg(Bptr + (size_t)t * DSq);
            float Ct = __ldg(Cptr + (size_t)t * DSq);
            float dA = __expf(dt * A);
            h = fmaf(dA, h, dt * ut * Bt);
            float p = h * Ct;
            p += __shfl_xor_sync(0xffffffffu, p, 8);
            p += __shfl_xor_sync(0xffffffffu, p, 4);
            p += __shfl_xor_sync(0xffffffffu, p, 2);
            p += __shfl_xor_sync(0xffffffffu, p, 1);
            if (s == 0) ybuf[ld][tc] = p;
        }
        __syncthreads();
        int fd = tid >> 4, ft = (tid & 15) * 4;
        size_t idx = ((size_t)b*DIq + d0 + fd)*Lq + t0 + ft;
        float4 yv = *(float4*)&ybuf[fd][ft];
        float4 uv = *(const float4*)&g_u[idx];
        float4 zv = *(const float4*)&g_z[idx];
        float Dp = D_param[d0 + fd];
        float4 r;
        r.x = (yv.x + uv.x * Dp) * silu_f(zv.x);
        r.y = (yv.y + uv.y * Dp) * silu_f(zv.y);
        r.z = (yv.z + uv.z * Dp) * silu_f(zv.z);
        r.w = (yv.w + uv.w * Dp) * silu_f(zv.w);
        *(float4*)&g_y[idx] = r;
        __syncthreads();
    }
}

// ---------------- launch ----------------
extern "C" void kernel_launch(void* const* d_in, const int* in_sizes, int n_in,
                              void* d_out, int out_size) {
    const float* x         = (const float*)d_in[0];
    const float* c         = (const float*)d_in[1];
    const float* ln_w      = (const float*)d_in[2];
    const float* ln_b      = (const float*)d_in[3];
    const float* ada_w     = (const float*)d_in[4];
    const float* ada_b     = (const float*)d_in[5];
    const float* in_proj_w = (const float*)d_in[6];
    const float* conv_w    = (const float*)d_in[7];
    const float* conv_b    = (const float*)d_in[8];
    const float* x_proj_w  = (const float*)d_in[9];
    const float* dt_proj_w = (const float*)d_in[10];
    const float* dt_proj_b = (const float*)d_in[11];
    const float* A_log     = (const float*)d_in[12];
    const float* D_param   = (const float*)d_in[13];
    const float* out_proj_w= (const float*)d_in[14];
    float* out = (float*)d_out;

    k_ada<<<9, 256>>>(c, ada_w, ada_b);            // launch 1
    k_ln<<<BLq, 256>>>(x, ln_w, ln_b);             // launch 2
    k_nop<<<1, 32>>>();                            // launch 3 (shifts profile slot)
    gemm_xz_bf<<<dim3(64, 24), 256>>>(in_proj_w);  // launch 4  <-- profiled
    k_conv<<<dim3(DIq, Bq), 256>>>(conv_w, conv_b);
    gemm_dbl_bf<<<dim3(64, 1), 256>>>(x_proj_w);
    gemm_delta_tc<<<dim3(64, 12), 256>>>(dt_proj_w, dt_proj_b);
    k_scan<<<dim3(DIq / 16, Bq), 256>>>(A_log, D_param);
    gemm_out_bf<<<dim3(64, 6), 256>>>(out_proj_w, x, out);
    (void)in_sizes; (void)n_in; (void)out_size;
}

// round 17
// speedup vs baseline: 1.0219x; 1.0219x over previous
#include <cuda_runtime.h>
#include <cuda_bf16.h>
#include <cstdint>

// Shapes (fixed by problem)
#define Bq   4
#define Lq   2048
#define Dq   768
#define DIq  1536
#define DSq  16
#define DRq  48
#define BLq  8192          // B*L
#define TWOD 1536          // 2*D
#define THREED 2304        // 3*D

// ---------------- scratch (static device memory; no allocation) ----------------
__device__ float g_ada[Bq * THREED];                 // [b][3D]  shift|scale|gate
__device__ float g_xm [BLq * Dq];                    // [bl][D]
__device__ float g_xi [Bq * DIq * Lq];               // [b][d][l]
__device__ float g_z  [Bq * DIq * Lq];               // [b][d][l]
__device__ float g_u  [Bq * DIq * Lq];               // [b][d][l]
__device__ float g_dt [BLq * DRq];                   // [bl][48]
__device__ float g_Bm [BLq * DSq];                   // [bl][16]
__device__ float g_Cm [BLq * DSq];                   // [bl][16]
__device__ float g_delta[Bq * DIq * Lq];             // [b][d][l]
__device__ float g_y  [Bq * DIq * Lq];               // [b][d][l]

__device__ __forceinline__ float silu_f(float x) {
    return x / (1.0f + __expf(-x));
}
__device__ __forceinline__ float softplus_f(float x) {
    return (x > 20.0f) ? x : log1pf(__expf(x));
}
__device__ __forceinline__ uint32_t f2tf32(float x) {
    uint32_t r;
    asm("cvt.rna.tf32.f32 %0, %1;" : "=r"(r) : "f"(x));
    return r;
}
__device__ __forceinline__ uint32_t f2bf2(float lo, float hi) {
    __nv_bfloat162 v = __floats2bfloat162_rn(lo, hi);
    return *(uint32_t*)&v;
}
__device__ __forceinline__ void mma_tf32(float (&d)[4], const uint32_t* a, const uint32_t* b) {
    asm volatile("mma.sync.aligned.m16n8k8.row.col.f32.tf32.tf32.f32 "
        "{%0,%1,%2,%3},{%4,%5,%6,%7},{%8,%9},{%0,%1,%2,%3};"
        : "+f"(d[0]), "+f"(d[1]), "+f"(d[2]), "+f"(d[3])
        : "r"(a[0]), "r"(a[1]), "r"(a[2]), "r"(a[3]), "r"(b[0]), "r"(b[1]));
}
__device__ __forceinline__ void mma_bf16(float (&d)[4], const uint32_t* a, const uint32_t* b) {
    asm volatile("mma.sync.aligned.m16n8k16.row.col.f32.bf16.bf16.f32 "
        "{%0,%1,%2,%3},{%4,%5,%6,%7},{%8,%9},{%0,%1,%2,%3};"
        : "+f"(d[0]), "+f"(d[1]), "+f"(d[2]), "+f"(d[3])
        : "r"(a[0]), "r"(a[1]), "r"(a[2]), "r"(a[3]), "r"(b[0]), "r"(b[1]));
}

// ---------------- instrumentation nop (keeps gemm_xz_bf in profiled slot #4) ----
__global__ void k_nop() {}

// ---------------- ada = silu(c) @ ada_w.T + ada_b ----------------
__global__ void k_ada(const float* __restrict__ c,
                      const float* __restrict__ ada_w,
                      const float* __restrict__ ada_b) {
    __shared__ float sc[Bq * TWOD];
    int tid = threadIdx.x;
    for (int i = tid; i < Bq * TWOD; i += blockDim.x) {
        float v = c[i];
        sc[i] = silu_f(v);
    }
    __syncthreads();
    int j = blockIdx.x * blockDim.x + tid;
    if (j >= THREED) return;
    float a0 = 0.f, a1 = 0.f, a2 = 0.f, a3 = 0.f;
    const float* w = ada_w + (size_t)j * TWOD;
    #pragma unroll 4
    for (int k = 0; k < TWOD; k += 4) {
        float4 wv = *(const float4*)(w + k);
        a0 += wv.x*sc[0*TWOD+k] + wv.y*sc[0*TWOD+k+1] + wv.z*sc[0*TWOD+k+2] + wv.w*sc[0*TWOD+k+3];
        a1 += wv.x*sc[1*TWOD+k] + wv.y*sc[1*TWOD+k+1] + wv.z*sc[1*TWOD+k+2] + wv.w*sc[1*TWOD+k+3];
        a2 += wv.x*sc[2*TWOD+k] + wv.y*sc[2*TWOD+k+1] + wv.z*sc[2*TWOD+k+2] + wv.w*sc[2*TWOD+k+3];
        a3 += wv.x*sc[3*TWOD+k] + wv.y*sc[3*TWOD+k+1] + wv.z*sc[3*TWOD+k+2] + wv.w*sc[3*TWOD+k+3];
    }
    float bb = ada_b[j];
    g_ada[0*THREED + j] = a0 + bb;
    g_ada[1*THREED + j] = a1 + bb;
    g_ada[2*THREED + j] = a2 + bb;
    g_ada[3*THREED + j] = a3 + bb;
}

// ---------------- LayerNorm + modulation ----------------
__global__ void k_ln(const float* __restrict__ x,
                     const float* __restrict__ ln_w,
                     const float* __restrict__ ln_b) {
    int row = blockIdx.x;            // bl
    int b = row >> 11;
    const float* xr = x + (size_t)row * Dq;
    int tid = threadIdx.x;
    float v0 = xr[tid], v1 = xr[tid + 256], v2 = xr[tid + 512];
    float s = v0 + v1 + v2;
    float sq = v0*v0 + v1*v1 + v2*v2;
    #pragma unroll
    for (int o = 16; o; o >>= 1) {
        s  += __shfl_xor_sync(0xffffffffu, s, o);
        sq += __shfl_xor_sync(0xffffffffu, sq, o);
    }
    __shared__ float ss[8], sqq[8];
    int lane = tid & 31, wid = tid >> 5;
    if (lane == 0) { ss[wid] = s; sqq[wid] = sq; }
    __syncthreads();
    float ts = 0.f, tq = 0.f;
    #pragma unroll
    for (int w = 0; w < 8; ++w) { ts += ss[w]; tq += sqq[w]; }
    float mu = ts * (1.0f / Dq);
    float var = tq * (1.0f / Dq) - mu * mu;
    float rs = rsqrtf(var + 1e-5f);
    float* dst = g_xm + (size_t)row * Dq;
    const float* sh = g_ada + b * THREED;        // shift
    const float* sc = g_ada + b * THREED + Dq;   // scale
    #pragma unroll
    for (int p = 0; p < 3; ++p) {
        int i = tid + p * 256;
        float v = (p == 0) ? v0 : (p == 1) ? v1 : v2;
        float xn = (v - mu) * rs * ln_w[i] + ln_b[i];
        dst[i] = xn * (1.0f + sc[i]) + sh[i];
    }
}

// ======================= bf16 m16n8k16 GEMMs, double-buffered ==================
// Block tile 128x128, BK=16 (8 k-pair rows), 8 warps (2x4), warp 64x32.
// 2-stage smem pipeline: ONE __syncthreads per K-chunk.
#define SST 136   // smem row stride in words

// xz = xm @ in_proj_w.T. A=in_proj_w (3072x768), B=g_xm (8192x768).
__global__ void __launch_bounds__(256)
gemm_xz_bf(const float* __restrict__ W) {
    __shared__ uint32_t As[2][8][SST];
    __shared__ uint32_t Bs[2][8][SST];
    const int K = Dq;
    const int NC = K / 16;          // 48
    int tid = threadIdx.x;
    int warp = tid >> 5, lane = tid & 31;
    int g = lane >> 2, t = lane & 3;
    int wm = (warp >> 2) * 64;
    int wn = (warp & 3) * 32;
    int nBase = blockIdx.y * 128;
    int mBase = blockIdx.x * 128;
    float acc[4][4][4];
    #pragma unroll
    for (int i = 0; i < 4; ++i)
        #pragma unroll
        for (int j = 0; j < 4; ++j)
            #pragma unroll
            for (int r = 0; r < 4; ++r) acc[i][j][r] = 0.f;

    int lrow = tid >> 2;
    int lk   = (tid & 3) * 4;
    int kp   = lk >> 1;
    const float* Arow0 = &W   [(size_t)(nBase + lrow)      * K + lk];
    const float* Arow1 = &W   [(size_t)(nBase + lrow + 64) * K + lk];
    const float* Brow0 = &g_xm[(size_t)(mBase + lrow)      * K + lk];
    const float* Brow1 = &g_xm[(size_t)(mBase + lrow + 64) * K + lk];

    float4 pa[2], pb[2];
    pa[0] = *(const float4*)Arow0;        pa[1] = *(const float4*)Arow1;
    pb[0] = *(const float4*)Brow0;        pb[1] = *(const float4*)Brow1;
    // store chunk 0 -> stage 0
    {
        As[0][kp+0][lrow] = f2bf2(pa[0].x, pa[0].y);
        As[0][kp+1][lrow] = f2bf2(pa[0].z, pa[0].w);
        As[0][kp+0][lrow+64] = f2bf2(pa[1].x, pa[1].y);
        As[0][kp+1][lrow+64] = f2bf2(pa[1].z, pa[1].w);
        Bs[0][kp+0][lrow] = f2bf2(pb[0].x, pb[0].y);
        Bs[0][kp+1][lrow] = f2bf2(pb[0].z, pb[0].w);
        Bs[0][kp+0][lrow+64] = f2bf2(pb[1].x, pb[1].y);
        Bs[0][kp+1][lrow+64] = f2bf2(pb[1].z, pb[1].w);
    }
    // prefetch chunk 1
    pa[0] = *(const float4*)(Arow0 + 16); pa[1] = *(const float4*)(Arow1 + 16);
    pb[0] = *(const float4*)(Brow0 + 16); pb[1] = *(const float4*)(Brow1 + 16);
    __syncthreads();

    for (int c = 0; c < NC; ++c) {
        int cur = c & 1;
        if (c + 1 < NC) {
            int nxt = cur ^ 1;
            As[nxt][kp+0][lrow] = f2bf2(pa[0].x, pa[0].y);
            As[nxt][kp+1][lrow] = f2bf2(pa[0].z, pa[0].w);
            As[nxt][kp+0][lrow+64] = f2bf2(pa[1].x, pa[1].y);
            As[nxt][kp+1][lrow+64] = f2bf2(pa[1].z, pa[1].w);
            Bs[nxt][kp+0][lrow] = f2bf2(pb[0].x, pb[0].y);
            Bs[nxt][kp+1][lrow] = f2bf2(pb[0].z, pb[0].w);
            Bs[nxt][kp+0][lrow+64] = f2bf2(pb[1].x, pb[1].y);
            Bs[nxt][kp+1][lrow+64] = f2bf2(pb[1].z, pb[1].w);
            if (c + 2 < NC) {
                int off = (c + 2) * 16;
                pa[0] = *(const float4*)(Arow0 + off); pa[1] = *(const float4*)(Arow1 + off);
                pb[0] = *(const float4*)(Brow0 + off); pb[1] = *(const float4*)(Brow1 + off);
            }
        }
        {
            uint32_t af[4][4], bf[4][2];
            #pragma unroll
            for (int mi = 0; mi < 4; ++mi) {
                int mr = wm + mi * 16 + g;
                af[mi][0] = As[cur][t][mr];     af[mi][1] = As[cur][t][mr+8];
                af[mi][2] = As[cur][t+4][mr];   af[mi][3] = As[cur][t+4][mr+8];
            }
            #pragma unroll
            for (int ni = 0; ni < 4; ++ni) {
                int nc = wn + ni * 8 + g;
                bf[ni][0] = Bs[cur][t][nc];
                bf[ni][1] = Bs[cur][t+4][nc];
            }
            #pragma unroll
            for (int mi = 0; mi < 4; ++mi)
                #pragma unroll
                for (int ni = 0; ni < 4; ++ni)
                    mma_bf16(acc[mi][ni], af[mi], bf[ni]);
        }
        __syncthreads();
    }
    int b = mBase >> 11;
    int l0 = (mBase & 2047) + wn;
    #pragma unroll
    for (int mi = 0; mi < 4; ++mi) {
        int n = nBase + wm + mi * 16 + g;
        #pragma unroll
        for (int ni = 0; ni < 4; ++ni) {
            int l = l0 + ni * 8 + 2 * t;
            float* d0 = (n < DIq) ? &g_xi[((size_t)b*DIq + n)*Lq]
                                  : &g_z [((size_t)b*DIq + (n - DIq))*Lq];
            int n2 = n + 8;
            float* d1 = (n2 < DIq) ? &g_xi[((size_t)b*DIq + n2)*Lq]
                                   : &g_z [((size_t)b*DIq + (n2 - DIq))*Lq];
            *(float2*)&d0[l] = make_float2(acc[mi][ni][0], acc[mi][ni][1]);
            *(float2*)&d1[l] = make_float2(acc[mi][ni][2], acc[mi][ni][3]);
        }
    }
}

// out = g @ out_proj_w.T (+x +gate*...). A=out_proj_w (768x1536), B=g_y[b][d][l].
__global__ void __launch_bounds__(256)
gemm_out_bf(const float* __restrict__ Wo, const float* __restrict__ x,
            float* __restrict__ out) {
    __shared__ uint32_t As[2][8][SST];
    __shared__ uint32_t Bs[2][8][SST];
    const int K = DIq;
    const int NC = K / 16;          // 96
    int tid = threadIdx.x;
    int warp = tid >> 5, lane = tid & 31;
    int g = lane >> 2, t = lane & 3;
    int wm = (warp >> 2) * 64;
    int wn = (warp & 3) * 32;
    int nBase = blockIdx.y * 128;
    int mBase = blockIdx.x * 128;
    int b = mBase >> 11;
    int l0b = mBase & 2047;
    float acc[4][4][4];
    #pragma unroll
    for (int i = 0; i < 4; ++i)
        #pragma unroll
        for (int j = 0; j < 4; ++j)
            #pragma unroll
            for (int r = 0; r < 4; ++r) acc[i][j][r] = 0.f;

    int lrow = tid >> 2;
    int lk   = (tid & 3) * 4;
    int kp   = lk >> 1;
    int kp8  = tid >> 5;
    int c4   = (tid & 31) * 4;
    const float* Arow0 = &Wo[(size_t)(nBase + lrow)      * K + lk];
    const float* Arow1 = &Wo[(size_t)(nBase + lrow + 64) * K + lk];
    const float* Be = &g_y[((size_t)b*DIq + 2*kp8    )*Lq + l0b + c4];
    const float* Bo = &g_y[((size_t)b*DIq + 2*kp8 + 1)*Lq + l0b + c4];

    float4 pa[2], pbe, pbo;
    pa[0] = *(const float4*)Arow0;  pa[1] = *(const float4*)Arow1;
    pbe = *(const float4*)Be;       pbo = *(const float4*)Bo;
    {
        As[0][kp+0][lrow]    = f2bf2(pa[0].x, pa[0].y);
        As[0][kp+1][lrow]    = f2bf2(pa[0].z, pa[0].w);
        As[0][kp+0][lrow+64] = f2bf2(pa[1].x, pa[1].y);
        As[0][kp+1][lrow+64] = f2bf2(pa[1].z, pa[1].w);
        uint4 wv;
        wv.x = f2bf2(pbe.x, pbo.x); wv.y = f2bf2(pbe.y, pbo.y);
        wv.z = f2bf2(pbe.z, pbo.z); wv.w = f2bf2(pbe.w, pbo.w);
        *(uint4*)&Bs[0][kp8][c4] = wv;
    }
    pa[0] = *(const float4*)(Arow0 + 16);
    pa[1] = *(const float4*)(Arow1 + 16);
    pbe = *(const float4*)(Be + 16 * Lq);
    pbo = *(const float4*)(Bo + 16 * Lq);
    __syncthreads();

    for (int c = 0; c < NC; ++c) {
        int cur = c & 1;
        if (c + 1 < NC) {
            int nxt = cur ^ 1;
            As[nxt][kp+0][lrow]    = f2bf2(pa[0].x, pa[0].y);
            As[nxt][kp+1][lrow]    = f2bf2(pa[0].z, pa[0].w);
            As[nxt][kp+0][lrow+64] = f2bf2(pa[1].x, pa[1].y);
            As[nxt][kp+1][lrow+64] = f2bf2(pa[1].z, pa[1].w);
            uint4 wv;
            wv.x = f2bf2(pbe.x, pbo.x); wv.y = f2bf2(pbe.y, pbo.y);
            wv.z = f2bf2(pbe.z, pbo.z); wv.w = f2bf2(pbe.w, pbo.w);
            *(uint4*)&Bs[nxt][kp8][c4] = wv;
            if (c + 2 < NC) {
                int off = (c + 2) * 16;
                pa[0] = *(const float4*)(Arow0 + off);
                pa[1] = *(const float4*)(Arow1 + off);
                pbe = *(const float4*)(Be + (size_t)off * Lq);
                pbo = *(const float4*)(Bo + (size_t)off * Lq);
            }
        }
        {
            uint32_t af[4][4], bf[4][2];
            #pragma unroll
            for (int mi = 0; mi < 4; ++mi) {
                int mr = wm + mi * 16 + g;
                af[mi][0] = As[cur][t][mr];     af[mi][1] = As[cur][t][mr+8];
                af[mi][2] = As[cur][t+4][mr];   af[mi][3] = As[cur][t+4][mr+8];
            }
            #pragma unroll
            for (int ni = 0; ni < 4; ++ni) {
                int nc = wn + ni * 8 + g;
                bf[ni][0] = Bs[cur][t][nc];
                bf[ni][1] = Bs[cur][t+4][nc];
            }
            #pragma unroll
            for (int mi = 0; mi < 4; ++mi)
                #pragma unroll
                for (int ni = 0; ni < 4; ++ni)
                    mma_bf16(acc[mi][ni], af[mi], bf[ni]);
        }
        __syncthreads();
    }
    const float* gate = g_ada + b * THREED + 2 * Dq;
    #pragma unroll
    for (int mi = 0; mi < 4; ++mi) {
        int n = nBase + wm + mi * 16 + g;
        float g0 = gate[n], g1 = gate[n + 8];
        #pragma unroll
        for (int ni = 0; ni < 4; ++ni) {
            int m = mBase + wn + ni * 8 + 2 * t;
            out[(size_t)m*Dq + n]       = x[(size_t)m*Dq + n]       + g0 * acc[mi][ni][0];
            out[(size_t)(m+1)*Dq + n]   = x[(size_t)(m+1)*Dq + n]   + g0 * acc[mi][ni][1];
            out[(size_t)m*Dq + n+8]     = x[(size_t)m*Dq + n+8]     + g1 * acc[mi][ni][2];
            out[(size_t)(m+1)*Dq + n+8] = x[(size_t)(m+1)*Dq + n+8] + g1 * acc[mi][ni][3];
        }
    }
}

// dbl = u @ x_proj_w.T scattered into g_dt/g_Bm/g_Cm.
__device__ __forceinline__ void store_dbl(int n, int m, float v) {
    if (n < DRq)             g_dt[(size_t)m * DRq + n] = v;
    else if (n < DRq + DSq)  g_Bm[(size_t)m * DSq + (n - DRq)] = v;
    else if (n < 80)         g_Cm[(size_t)m * DSq + (n - DRq - DSq)] = v;
}
__global__ void __launch_bounds__(256)
gemm_dbl_bf(const float* __restrict__ Wx) {
    __shared__ uint32_t As[2][8][SST];
    __shared__ uint32_t Bs[2][8][SST];
    const int K = DIq;
    const int NC = K / 16;          // 96
    int tid = threadIdx.x;
    int warp = tid >> 5, lane = tid & 31;
    int g = lane >> 2, t = lane & 3;
    int wm = (warp >> 2) * 64;
    int wn = (warp & 3) * 32;
    int mBase = blockIdx.x * 128;
    int b = mBase >> 11;
    int l0b = mBase & 2047;
    float acc[4][4][4];
    #pragma unroll
    for (int i = 0; i < 4; ++i)
        #pragma unroll
        for (int j = 0; j < 4; ++j)
            #pragma unroll
            for (int r = 0; r < 4; ++r) acc[i][j][r] = 0.f;

    int lrow = tid >> 2;
    int lk   = (tid & 3) * 4;
    int kp   = lk >> 1;
    int kp8  = tid >> 5;
    int c4   = (tid & 31) * 4;
    int ar0 = min(lrow, 79);
    int ar1 = min(lrow + 64, 79);
    const float* Arow0 = &Wx[(size_t)ar0 * K + lk];
    const float* Arow1 = &Wx[(size_t)ar1 * K + lk];
    const float* Be = &g_u[((size_t)b*DIq + 2*kp8    )*Lq + l0b + c4];
    const float* Bo = &g_u[((size_t)b*DIq + 2*kp8 + 1)*Lq + l0b + c4];

    float4 pa[2], pbe, pbo;
    pa[0] = *(const float4*)Arow0;  pa[1] = *(const float4*)Arow1;
    pbe = *(const float4*)Be;       pbo = *(const float4*)Bo;
    {
        As[0][kp+0][lrow]    = f2bf2(pa[0].x, pa[0].y);
        As[0][kp+1][lrow]    = f2bf2(pa[0].z, pa[0].w);
        As[0][kp+0][lrow+64] = f2bf2(pa[1].x, pa[1].y);
        As[0][kp+1][lrow+64] = f2bf2(pa[1].z, pa[1].w);
        uint4 wv;
        wv.x = f2bf2(pbe.x, pbo.x); wv.y = f2bf2(pbe.y, pbo.y);
        wv.z = f2bf2(pbe.z, pbo.z); wv.w = f2bf2(pbe.w, pbo.w);
        *(uint4*)&Bs[0][kp8][c4] = wv;
    }
    pa[0] = *(const float4*)(Arow0 + 16);
    pa[1] = *(const float4*)(Arow1 + 16);
    pbe = *(const float4*)(Be + 16 * Lq);
    pbo = *(const float4*)(Bo + 16 * Lq);
    __syncthreads();

    for (int c = 0; c < NC; ++c) {
        int cur = c & 1;
        if (c + 1 < NC) {
            int nxt = cur ^ 1;
            As[nxt][kp+0][lrow]    = f2bf2(pa[0].x, pa[0].y);
            As[nxt][kp+1][lrow]    = f2bf2(pa[0].z, pa[0].w);
            As[nxt][kp+0][lrow+64] = f2bf2(pa[1].x, pa[1].y);
            As[nxt][kp+1][lrow+64] = f2bf2(pa[1].z, pa[1].w);
            uint4 wv;
            wv.x = f2bf2(pbe.x, pbo.x); wv.y = f2bf2(pbe.y, pbo.y);
            wv.z = f2bf2(pbe.z, pbo.z); wv.w = f2bf2(pbe.w, pbo.w);
            *(uint4*)&Bs[nxt][kp8][c4] = wv;
            if (c + 2 < NC) {
                int off = (c + 2) * 16;
                pa[0] = *(const float4*)(Arow0 + off);
                pa[1] = *(const float4*)(Arow1 + off);
                pbe = *(const float4*)(Be + (size_t)off * Lq);
                pbo = *(const float4*)(Bo + (size_t)off * Lq);
            }
        }
        {
            uint32_t af[4][4], bf[4][2];
            #pragma unroll
            for (int mi = 0; mi < 4; ++mi) {
                int mr = wm + mi * 16 + g;
                af[mi][0] = As[cur][t][mr];     af[mi][1] = As[cur][t][mr+8];
                af[mi][2] = As[cur][t+4][mr];   af[mi][3] = As[cur][t+4][mr+8];
            }
            #pragma unroll
            for (int ni = 0; ni < 4; ++ni) {
                int nc = wn + ni * 8 + g;
                bf[ni][0] = Bs[cur][t][nc];
                bf[ni][1] = Bs[cur][t+4][nc];
            }
            #pragma unroll
            for (int mi = 0; mi < 4; ++mi)
                #pragma unroll
                for (int ni = 0; ni < 4; ++ni)
                    mma_bf16(acc[mi][ni], af[mi], bf[ni]);
        }
        __syncthreads();
    }
    #pragma unroll
    for (int mi = 0; mi < 4; ++mi) {
        int n = wm + mi * 16 + g;
        if (n >= 80 && n + 8 >= 80) continue;
        #pragma unroll
        for (int ni = 0; ni < 4; ++ni) {
            int m = mBase + wn + ni * 8 + 2 * t;
            store_dbl(n,     m,     acc[mi][ni][0]);
            store_dbl(n,     m + 1, acc[mi][ni][1]);
            store_dbl(n + 8, m,     acc[mi][ni][2]);
            store_dbl(n + 8, m + 1, acc[mi][ni][3]);
        }
    }
}

// ======================= TF32 delta GEMM (unchanged, passing) ===================
#define SSTD 136
__global__ void __launch_bounds__(256)
gemm_delta_tc(const float* __restrict__ Wd, const float* __restrict__ dt_b) {
    __shared__ uint32_t As[16][SSTD];
    __shared__ uint32_t Bs[16][SSTD];
    const int K = DRq;              // 48
    int tid = threadIdx.x;
    int warp = tid >> 5, lane = tid & 31;
    int g = lane >> 2, t = lane & 3;
    int wm = (warp >> 2) * 64;
    int wn = (warp & 3) * 32;
    int nBase = blockIdx.y * 128;
    int mBase = blockIdx.x * 128;
    float acc[4][4][4];
    #pragma unroll
    for (int i = 0; i < 4; ++i)
        #pragma unroll
        for (int j = 0; j < 4; ++j)
            #pragma unroll
            for (int r = 0; r < 4; ++r) acc[i][j][r] = 0.f;

    int lrow = tid >> 2;
    int lk   = (tid & 3) * 4;
    float4 pa[2], pb[2];
    #pragma unroll
    for (int h = 0; h < 2; ++h) {
        pa[h] = *(const float4*)&Wd  [(size_t)(nBase + lrow + h*64) * K + lk];
        pb[h] = *(const float4*)&g_dt[(size_t)(mBase + lrow + h*64) * K + lk];
    }
    for (int k0 = 0; k0 < K; k0 += 16) {
        #pragma unroll
        for (int h = 0; h < 2; ++h) {
            int r = lrow + h * 64;
            As[lk+0][r] = f2tf32(pa[h].x); As[lk+1][r] = f2tf32(pa[h].y);
            As[lk+2][r] = f2tf32(pa[h].z); As[lk+3][r] = f2tf32(pa[h].w);
            Bs[lk+0][r] = f2tf32(pb[h].x); Bs[lk+1][r] = f2tf32(pb[h].y);
            Bs[lk+2][r] = f2tf32(pb[h].z); Bs[lk+3][r] = f2tf32(pb[h].w);
        }
        __syncthreads();
        if (k0 + 16 < K) {
            #pragma unroll
            for (int h = 0; h < 2; ++h) {
                pa[h] = *(const float4*)&Wd  [(size_t)(nBase + lrow + h*64) * K + k0 + 16 + lk];
                pb[h] = *(const float4*)&g_dt[(size_t)(mBase + lrow + h*64) * K + k0 + 16 + lk];
            }
        }
        #pragma unroll
        for (int kk = 0; kk < 16; kk += 8) {
            uint32_t af[4][4], bf[4][2];
            #pragma unroll
            for (int mi = 0; mi < 4; ++mi) {
                int mr = wm + mi * 16 + g;
                af[mi][0] = As[kk+t][mr];     af[mi][1] = As[kk+t][mr+8];
                af[mi][2] = As[kk+t+4][mr];   af[mi][3] = As[kk+t+4][mr+8];
            }
            #pragma unroll
            for (int ni = 0; ni < 4; ++ni) {
                int nc = wn + ni * 8 + g;
                bf[ni][0] = Bs[kk+t][nc];
                bf[ni][1] = Bs[kk+t+4][nc];
            }
            #pragma unroll
            for (int mi = 0; mi < 4; ++mi)
                #pragma unroll
                for (int ni = 0; ni < 4; ++ni)
                    mma_tf32(acc[mi][ni], af[mi], bf[ni]);
        }
        __syncthreads();
    }
    int b = mBase >> 11;
    int l0 = (mBase & 2047) + wn;
    #pragma unroll
    for (int mi = 0; mi < 4; ++mi) {
        int n = nBase + wm + mi * 16 + g;
        float b0 = dt_b[n], b1 = dt_b[n + 8];
        float* d0 = &g_delta[((size_t)b*DIq + n)*Lq];
        float* d1 = &g_delta[((size_t)b*DIq + n + 8)*Lq];
        #pragma unroll
        for (int ni = 0; ni < 4; ++ni) {
            int l = l0 + ni * 8 + 2 * t;
            *(float2*)&d0[l] = make_float2(softplus_f(acc[mi][ni][0] + b0),
                                           softplus_f(acc[mi][ni][1] + b0));
            *(float2*)&d1[l] = make_float2(softplus_f(acc[mi][ni][2] + b1),
                                           softplus_f(acc[mi][ni][3] + b1));
        }
    }
}

// ---------------- depthwise causal conv(K=4) + SiLU -> u ----------------
__global__ void k_conv(const float* __restrict__ conv_w,
                       const float* __restrict__ conv_b) {
    int d = blockIdx.x, b = blockIdx.y;
    __shared__ float s[Lq + 4];
    const float* src = &g_xi[((size_t)b*DIq + d)*Lq];
    int tid = threadIdx.x;
    if (tid < 3) s[tid + 1] = 0.f;
    *(float4*)&s[4 + tid*8]     = *(const float4*)&src[tid*8];
    *(float4*)&s[4 + tid*8 + 4] = *(const float4*)&src[tid*8 + 4];
    __syncthreads();
    float w0 = conv_w[d*4+0], w1 = conv_w[d*4+1], w2 = conv_w[d*4+2], w3 = conv_w[d*4+3];
    float cb = conv_b[d];
    float out[8];
    int base = tid * 8;
    #pragma unroll
    for (int i = 0; i < 8; ++i) {
        int l = base + i;
        float acc = w0*s[l+1] + w1*s[l+2] + w2*s[l+3] + w3*s[l+4] + cb;
        out[i] = silu_f(acc);
    }
    float* dst = &g_u[((size_t)b*DIq + d)*Lq + base];
    *(float4*)&dst[0] = make_float4(out[0], out[1], out[2], out[3]);
    *(float4*)&dst[4] = make_float4(out[4], out[5], out[6], out[7]);
}

// ---------------- selective scan + fused gate ----------------
__global__ void k_scan(const float* __restrict__ A_log,
                       const float* __restrict__ D_param) {
    int b = blockIdx.y;
    int d0 = blockIdx.x * 16;
    int tid = threadIdx.x;
    int ld = tid >> 4, s = tid & 15;
    int d = d0 + ld;
    float A = -__expf(A_log[d * DSq + s]);
    const float* dptr = &g_delta[((size_t)b*DIq + d)*Lq];
    const float* uptr = &g_u   [((size_t)b*DIq + d)*Lq];
    const float* Bptr = &g_Bm[(size_t)b*Lq*DSq + s];
    const float* Cptr = &g_Cm[(size_t)b*Lq*DSq + s];
    __shared__ float ybuf[16][64];
    float h = 0.f;
    for (int t0 = 0; t0 < Lq; t0 += 64) {
        #pragma unroll 4
        for (int tc = 0; tc < 64; ++tc) {
            int t = t0 + tc;
            float dt = __ldg(dptr + t);
            float ut = __ldg(uptr + t);
            float Bt = __ldg(Bptr + (size_t)t * DSq);
            float Ct = __ldg(Cptr + (size_t)t * DSq);
            float dA = __expf(dt * A);
            h = fmaf(dA, h, dt * ut * Bt);
            float p = h * Ct;
            p += __shfl_xor_sync(0xffffffffu, p, 8);
            p += __shfl_xor_sync(0xffffffffu, p, 4);
            p += __shfl_xor_sync(0xffffffffu, p, 2);
            p += __shfl_xor_sync(0xffffffffu, p, 1);
            if (s == 0) ybuf[ld][tc] = p;
        }
        __syncthreads();
        int fd = tid >> 4, ft = (tid & 15) * 4;
        size_t idx = ((size_t)b*DIq + d0 + fd)*Lq + t0 + ft;
        float4 yv = *(float4*)&ybuf[fd][ft];
        float4 uv = *(const float4*)&g_u[idx];
        float4 zv = *(const float4*)&g_z[idx];
        float Dp = D_param[d0 + fd];
        float4 r;
        r.x = (yv.x + uv.x * Dp) * silu_f(zv.x);
        r.y = (yv.y + uv.y * Dp) * silu_f(zv.y);
        r.z = (yv.z + uv.z * Dp) * silu_f(zv.z);
        r.w = (yv.w + uv.w * Dp) * silu_f(zv.w);
        *(float4*)&g_y[idx] = r;
        __syncthreads();
    }
}

// ---------------- launch ----------------
extern "C" void kernel_launch(void* const* d_in, const int* in_sizes, int n_in,
                              void* d_out, int out_size) {
    const float* x         = (const float*)d_in[0];
    const float* c         = (const float*)d_in[1];
    const float* ln_w      = (const float*)d_in[2];
    const float* ln_b      = (const float*)d_in[3];
    const float* ada_w     = (const float*)d_in[4];
    const float* ada_b     = (const float*)d_in[5];
    const float* in_proj_w = (const float*)d_in[6];
    const float* conv_w    = (const float*)d_in[7];
    const float* conv_b    = (const float*)d_in[8];
    const float* x_proj_w  = (const float*)d_in[9];
    const float* dt_proj_w = (const float*)d_in[10];
    const float* dt_proj_b = (const float*)d_in[11];
    const float* A_log     = (const float*)d_in[12];
    const float* D_param   = (const float*)d_in[13];
    const float* out_proj_w= (const float*)d_in[14];
    float* out = (float*)d_out;

    k_ada<<<9, 256>>>(c, ada_w, ada_b);            // launch 1
    k_ln<<<BLq, 256>>>(x, ln_w, ln_b);             // launch 2
    k_nop<<<1, 32>>>();                            // launch 3 (profile slot shift)
    gemm_xz_bf<<<dim3(64, 24), 256>>>(in_proj_w);  // launch 4  <-- profiled
    k_conv<<<dim3(DIq, Bq), 256>>>(conv_w, conv_b);
    gemm_dbl_bf<<<dim3(64, 1), 256>>>(x_proj_w);
    gemm_delta_tc<<<dim3(64, 12), 256>>>(dt_proj_w, dt_proj_b);
    k_scan<<<dim3(DIq / 16, Bq), 256>>>(A_log, D_param);
    gemm_out_bf<<<dim3(64, 6), 256>>>(out_proj_w, x, out);
    (void)in_sizes; (void)n_in; (void)out_size;
}